// round 2
// baseline (speedup 1.0000x reference)
#include <cuda_runtime.h>
#include <math.h>
#include <float.h>
#include <stdint.h>

#define BB 32
#define CC 64
#define LL 8192
#define NWIN 1021
#define MAXSEG 1024
#define MAXTOK 2176
#define PEN 3.0

// ---------------- device scratch (no allocations allowed) ----------------
__device__ float  g_agg[BB][LL];
__device__ float  g_feat[BB][NWIN][3];
__device__ double g_c32[32], g_s32[32];
__device__ int    g_seg_s[BB][MAXSEG], g_seg_e[BB][MAXSEG], g_nseg[BB];
__device__ float  g_dp[BB][MAXSEG], g_bw[BB][MAXSEG];
__device__ int    g_ts[BB][MAXTOK], g_te[BB][MAXTOK];
__device__ float  g_rgm[BB][MAXTOK][3];
__device__ int    g_ntok[BB];

// ---------------- init: 32-pt DFT twiddles ----------------
__global__ void k_init() {
    int t = threadIdx.x;
    double s, c;
    sincospi((double)t / 16.0, &s, &c);   // angle 2*pi*t/32 = pi*t/16
    g_c32[t] = c;
    g_s32[t] = s;
}

// ---------------- agg = mean over channels (sequential fp32, numpy order) ----------------
__global__ void k_agg(const float* __restrict__ x) {
    int b = blockIdx.y;
    int t = blockIdx.x * blockDim.x + threadIdx.x;
    const float* xb = x + ((size_t)b * CC) * LL + t;
    float s = 0.0f;
    #pragma unroll 1
    for (int c = 0; c < CC; c++) s += xb[(size_t)c * LL];
    g_agg[b][t] = s / 64.0f;
}

// ---------------- window features: 1 warp per window ----------------
// lanes 0..15 compute bins 1..16 (lanes 16..31 mirror). numpy pairwise-sum16
// reproduced exactly by xor-shuffle butterflies in order 8,1,2,4.
__global__ void k_winfeat() {
    int b = blockIdx.y;
    int widx = blockIdx.x * 8 + (threadIdx.x >> 5);
    if (widx >= NWIN) return;
    int lane = threadIdx.x & 31;
    int k = (lane & 15) + 1;
    int st = widx * 8;

    double re = 0.0, im = 0.0;
    #pragma unroll 1
    for (int t = 0; t < 32; t++) {
        double a = (double)g_agg[b][st + t];
        int id = (k * t) & 31;
        re = fma(a, g_c32[id], re);
        im = fma(a, g_s32[id], im);
    }
    double p = re * re + im * im;

    double tot = p;
    tot = tot + __shfl_xor_sync(0xffffffffu, tot, 8);
    tot = tot + __shfl_xor_sync(0xffffffffu, tot, 1);
    tot = tot + __shfl_xor_sync(0xffffffffu, tot, 2);
    tot = tot + __shfl_xor_sync(0xffffffffu, tot, 4);

    double prob = p / (tot + 1e-12);
    double f = (double)k / 32.0;

    double cen = prob * f;
    cen = cen + __shfl_xor_sync(0xffffffffu, cen, 8);
    cen = cen + __shfl_xor_sync(0xffffffffu, cen, 1);
    cen = cen + __shfl_xor_sync(0xffffffffu, cen, 2);
    cen = cen + __shfl_xor_sync(0xffffffffu, cen, 4);

    double dev = f - cen;
    double s2 = prob * (dev * dev);
    s2 = s2 + __shfl_xor_sync(0xffffffffu, s2, 8);
    s2 = s2 + __shfl_xor_sync(0xffffffffu, s2, 1);
    s2 = s2 + __shfl_xor_sync(0xffffffffu, s2, 2);
    s2 = s2 + __shfl_xor_sync(0xffffffffu, s2, 4);

    if (lane == 0) {
        double spread = sqrt(fmax(s2, 0.0));
        g_feat[b][widx][0] = (float)cen;
        g_feat[b][widx][1] = (float)(2.0 * spread);
        g_feat[b][widx][2] = (float)log1p(tot / 32.0);
    }
}

// ---------------- DP changepoints + boundary filtering + segment emit ----------------
// one block (1024 threads) per batch. fp64.
extern __shared__ char dpsm[];
__global__ void __launch_bounds__(1024, 1) k_dp() {
    const int n = NWIN;             // 1021
    int b = blockIdx.x;
    int tid = threadIdx.x;

    double* cs  = (double*)dpsm;        // (n+1)*3 = 3066
    double* A   = cs + 3066;            // n+1
    double* nn  = A + 1022;
    double* G   = nn + 1022;
    double* Fv  = G + 1022;
    double* rcp = Fv + 1022;
    double* rv  = rcp + 1022;           // 32
    int*    par = (int*)(rv + 32);      // 1024
    int*    ri  = par + 1024;           // 32

    if (tid == 0) {
        cs[0] = cs[1] = cs[2] = 0.0;
        A[0] = 0.0;
        double c0 = 0, c1 = 0, c2 = 0, q0 = 0, q1 = 0, q2 = 0;
        for (int i = 0; i < n; i++) {
            double f0 = (double)g_feat[b][i][0];
            double f1 = (double)g_feat[b][i][1];
            double f2 = (double)g_feat[b][i][2];
            c0 += f0; c1 += f1; c2 += f2;
            q0 += f0 * f0; q1 += f1 * f1; q2 += f2 * f2;
            cs[(i + 1) * 3 + 0] = c0;
            cs[(i + 1) * 3 + 1] = c1;
            cs[(i + 1) * 3 + 2] = c2;
            A[i + 1] = (q0 + q1) + q2;
        }
        Fv[0] = 0.0; G[0] = PEN; par[0] = 0;
    }
    for (int i = tid; i <= n; i += blockDim.x) rcp[i] = (i > 0) ? (1.0 / (double)i) : 0.0;
    __syncthreads();
    for (int i = tid; i <= n; i += blockDim.x) {
        double a0 = cs[i * 3], a1 = cs[i * 3 + 1], a2 = cs[i * 3 + 2];
        nn[i] = a0 * a0 + a1 * a1 + a2 * a2;
    }
    __syncthreads();

    int warp = tid >> 5, lane = tid & 31;
    for (int t = 1; t <= n; t++) {
        double ct0 = cs[t * 3], ct1 = cs[t * 3 + 1], ct2 = cs[t * 3 + 2];
        double nt = nn[t];
        double v; int idx;
        if (tid < t) {
            int j = tid;
            double dot = fma(ct2, cs[j * 3 + 2], fma(ct1, cs[j * 3 + 1], ct0 * cs[j * 3 + 0]));
            double u = fma(-2.0, dot, nt + nn[j]);   // sum of squared diffs
            v = fma(-u, rcp[t - j], G[j]);           // score = G[j] - u/(t-j)
            idx = j;
        } else { v = DBL_MAX; idx = 0x7fffffff; }
        #pragma unroll
        for (int o = 16; o; o >>= 1) {
            double ov = __shfl_down_sync(0xffffffffu, v, o);
            int oi = __shfl_down_sync(0xffffffffu, idx, o);
            if (ov < v || (ov == v && oi < idx)) { v = ov; idx = oi; }
        }
        if (lane == 0) { rv[warp] = v; ri[warp] = idx; }
        __syncthreads();
        if (warp == 0) {
            v = rv[lane]; idx = ri[lane];
            #pragma unroll
            for (int o = 16; o; o >>= 1) {
                double ov = __shfl_down_sync(0xffffffffu, v, o);
                int oi = __shfl_down_sync(0xffffffffu, idx, o);
                if (ov < v || (ov == v && oi < idx)) { v = ov; idx = oi; }
            }
            if (lane == 0) {
                int j = idx;
                double d0 = ct0 - cs[j * 3], d1 = ct1 - cs[j * 3 + 1], d2 = ct2 - cs[j * 3 + 2];
                double ss = (d0 * d0 + d1 * d1) + d2 * d2;
                double cost = (A[t] - A[j]) - ss / (double)(t - j);
                double fv = Fv[j] + cost + PEN;
                Fv[t] = fv;
                G[t] = (fv + PEN) - A[t];
                par[t] = j;
            }
        }
        __syncthreads();
    }

    if (tid == 0) {
        // backtrack (parents strictly decrease)
        int* chain = (int*)cs;   // reuse
        int cl = 0, t = n;
        chain[cl++] = t;
        while (t > 0) { t = par[t]; chain[cl++] = t; }
        // ascending middles: chain[cl-2] .. chain[1]
        int last = 0, nseg = 0;
        for (int q = cl - 2; q >= 1; q--) {
            int w = chain[q];
            if (w < 0 || w >= NWIN) continue;
            int ti = w * 8;
            if (ti <= last) continue;
            if (ti - last < 8) continue;
            if (LL - ti < 8) continue;
            g_seg_s[b][nseg] = last; g_seg_e[b][nseg] = ti; nseg++;
            last = ti;
        }
        g_seg_s[b][nseg] = last; g_seg_e[b][nseg] = LL; nseg++;
        g_nseg[b] = nseg;
    }
}

// ---------------- block reduce helpers (512 threads = 16 warps) ----------------
__device__ __forceinline__ double block_sum512(double v, double* sh) {
    int tid = threadIdx.x;
    #pragma unroll
    for (int o = 16; o; o >>= 1) v += __shfl_down_sync(0xffffffffu, v, o);
    if ((tid & 31) == 0) sh[tid >> 5] = v;
    __syncthreads();
    if (tid < 32) {
        double w = (tid < 16) ? sh[tid] : 0.0;
        #pragma unroll
        for (int o = 8; o; o >>= 1) w += __shfl_down_sync(0xffffffffu, w, o);
        if (tid == 0) sh[0] = w;
    }
    __syncthreads();
    double r = sh[0];
    __syncthreads();
    return r;
}

__device__ __forceinline__ void block_argmax512(double v, int k, double* shv, int* shk,
                                                double* outv, int* outk) {
    int tid = threadIdx.x;
    #pragma unroll
    for (int o = 16; o; o >>= 1) {
        double ov = __shfl_down_sync(0xffffffffu, v, o);
        int ok = __shfl_down_sync(0xffffffffu, k, o);
        if (ov > v || (ov == v && ok < k)) { v = ov; k = ok; }
    }
    if ((tid & 31) == 0) { shv[tid >> 5] = v; shk[tid >> 5] = k; }
    __syncthreads();
    if (tid < 32) {
        double w = (tid < 16) ? shv[tid] : -DBL_MAX;
        int kk = (tid < 16) ? shk[tid] : 0x7fffffff;
        #pragma unroll
        for (int o = 8; o; o >>= 1) {
            double ov = __shfl_down_sync(0xffffffffu, w, o);
            int ok = __shfl_down_sync(0xffffffffu, kk, o);
            if (ov > w || (ov == w && ok < kk)) { w = ov; kk = ok; }
        }
        if (tid == 0) { shv[0] = w; shk[0] = kk; }
    }
    __syncthreads();
    *outv = shv[0]; *outk = shk[0];
    __syncthreads();
}

// ---------------- per-segment spectral stats ----------------
// pow2 length: in-shared radix-2 fp64 FFT. otherwise: direct DFT with shared twiddle tables.
extern __shared__ char ssm[];
__global__ void __launch_bounds__(512, 1) k_segstats() {
    int b = blockIdx.y;
    int tid = threadIdx.x;
    const int T = 512;
    int nseg = g_nseg[b];

    double* re = (double*)ssm;       // 8192
    double* im = re + 8192;          // 8192
    double* parr = im + 8192;        // 4096 (fallback path)
    __shared__ double s_rv[16];
    __shared__ int s_rk[16];

    for (int seg = blockIdx.x; seg < nseg; seg += gridDim.x) {
        int s = g_seg_s[b][seg], e = g_seg_e[b][seg];
        int m = e - s;
        int K = m >> 1;
        double tot, maxv; int kbest;

        if ((m & (m - 1)) == 0) {
            int lg = __ffs(m) - 1;
            for (int i = tid; i < m; i += T) {
                unsigned r = __brev((unsigned)i) >> (32 - lg);
                re[r] = (double)g_agg[b][s + i];
                im[r] = 0.0;
            }
            __syncthreads();
            for (int len = 2; len <= m; len <<= 1) {
                int half = len >> 1;
                double inv = -2.0 / (double)len;
                for (int idx = tid; idx < (m >> 1); idx += T) {
                    int j = idx & (half - 1);
                    int pos = 2 * idx - j;
                    int p2 = pos + half;
                    double wc, ws;
                    sincospi(inv * (double)j, &ws, &wc);
                    double xr = re[p2], xi = im[p2];
                    double tr = wc * xr - ws * xi;
                    double ti = wc * xi + ws * xr;
                    double ur = re[pos], ui = im[pos];
                    re[pos] = ur + tr; im[pos] = ui + ti;
                    re[p2] = ur - tr;  im[p2] = ui - ti;
                }
                __syncthreads();
            }
            // pass1: total + argmax
            double lt = 0.0, lm = -DBL_MAX; int lk = 0x7fffffff;
            for (int k = 1 + tid; k <= K; k += T) {
                double pr = re[k] * re[k] + im[k] * im[k];
                lt += pr;
                if (pr > lm) { lm = pr; lk = k; }
            }
            tot = block_sum512(lt, s_rv);
            block_argmax512(lm, lk, s_rv, s_rk, &maxv, &kbest);
            double den = tot + 1e-12;
            double lc = 0.0;
            for (int k = 1 + tid; k <= K; k += T) {
                double pr = re[k] * re[k] + im[k] * im[k];
                lc += (pr / den) * ((double)k / (double)m);
            }
            double cen = block_sum512(lc, s_rv);
            double ls = 0.0;
            for (int k = 1 + tid; k <= K; k += T) {
                double pr = re[k] * re[k] + im[k] * im[k];
                double d = (double)k / (double)m - cen;
                ls += (pr / den) * (d * d);
            }
            double s2 = block_sum512(ls, s_rv);
            if (tid == 0) {
                double spread = sqrt(fmax(s2, 0.0));
                g_dp[b][seg] = (float)((double)m / (double)kbest);
                g_bw[b][seg] = (float)(2.0 * spread);
            }
            __syncthreads();
        } else {
            // direct DFT fallback: shared twiddle tables, incremental index
            for (int t = tid; t < m; t += T) {
                double a = 2.0 * (double)t / (double)m;
                double sv, cv;
                sincospi(a, &sv, &cv);
                re[t] = cv; im[t] = sv;
            }
            __syncthreads();
            for (int k = 1 + tid; k <= K; k += T) {
                double rr = 0.0, ri2 = 0.0;
                int idx = 0;
                for (int t = 0; t < m; t++) {
                    double a = (double)g_agg[b][s + t];
                    rr = fma(a, re[idx], rr);
                    ri2 = fma(a, im[idx], ri2);
                    idx += k; if (idx >= m) idx -= m;
                }
                parr[k - 1] = rr * rr + ri2 * ri2;
            }
            __syncthreads();
            double lt = 0.0, lm = -DBL_MAX; int lk = 0x7fffffff;
            for (int k = 1 + tid; k <= K; k += T) {
                double pr = parr[k - 1];
                lt += pr;
                if (pr > lm) { lm = pr; lk = k; }
            }
            tot = block_sum512(lt, s_rv);
            block_argmax512(lm, lk, s_rv, s_rk, &maxv, &kbest);
            double den = tot + 1e-12;
            double lc = 0.0;
            for (int k = 1 + tid; k <= K; k += T)
                lc += (parr[k - 1] / den) * ((double)k / (double)m);
            double cen = block_sum512(lc, s_rv);
            double ls = 0.0;
            for (int k = 1 + tid; k <= K; k += T) {
                double d = (double)k / (double)m - cen;
                ls += (parr[k - 1] / den) * (d * d);
            }
            double s2 = block_sum512(ls, s_rv);
            if (tid == 0) {
                double spread = sqrt(fmax(s2, 0.0));
                g_dp[b][seg] = (float)((double)m / (double)kbest);
                g_bw[b][seg] = (float)(2.0 * spread);
            }
            __syncthreads();
        }
    }
}

// ---------------- token generation (serial per batch; cheap) ----------------
__global__ void k_tokens() {
    int b = blockIdx.x;
    if (threadIdx.x != 0) return;
    int nseg = g_nseg[b];
    int n = 0;
    for (int sg = 0; sg < nseg; sg++) {
        int s = g_seg_s[b][sg], e = g_seg_e[b][sg];
        double dp = (double)g_dp[b][sg];
        double bw = (double)g_bw[b][sg];
        double raw = dp / (1.0 + bw);
        long long p = 2LL * (long long)rint(raw / 2.0);  // Python round: half-to-even
        long long pl = p;
        if (pl > 64) pl = 64;
        if (pl < 8) pl = 8;       // max(1, max(8, min(64, p)))
        float r0 = (float)(dp / 8192.0);
        float r1 = g_bw[b][sg];
        float r2 = (float)((double)(e - s) / 8192.0);
        int ipl = (int)pl;
        int nf = (e - s) / ipl;
        for (int i = 0; i < nf && n < MAXTOK; i++) {
            g_ts[b][n] = s + i * ipl;
            g_te[b][n] = s + (i + 1) * ipl;
            g_rgm[b][n][0] = r0; g_rgm[b][n][1] = r1; g_rgm[b][n][2] = r2;
            n++;
        }
        if (nf * ipl < e - s && n < MAXTOK) {
            g_ts[b][n] = s + nf * ipl;
            g_te[b][n] = e;
            g_rgm[b][n][0] = r0; g_rgm[b][n][1] = r1; g_rgm[b][n][2] = r2;
            n++;
        }
    }
    g_ntok[b] = n;
}

// ---------------- output writer ----------------
// layout 0: all outputs concatenated as float32
// layout 1: byte concat, mask u8, so/eo/n_tok int32
// layout 2: byte concat, mask u8, so/eo/n_tok int64
__global__ void k_write(const float* __restrict__ x, char* __restrict__ out,
                        long long N, int layout) {
    int b = blockIdx.y;
    long long tok = blockIdx.x;
    int tid = threadIdx.x;
    int nt = g_ntok[b];
    bool valid = tok < (long long)nt;

    __shared__ int sh_i0[16], sh_i1[16];
    __shared__ float sh_w[16];

    int s = 0, e = 16;
    if (valid) { s = g_ts[b][tok]; e = g_te[b][tok]; }
    int plen = e - s;

    if (tid < 16) {
        float scale = (float)((double)plen / 16.0);
        float pos = ((float)tid + 0.5f) * scale - 0.5f;
        pos = fminf(fmaxf(pos, 0.0f), (float)(plen - 1));
        int i0 = (int)floorf(pos);
        int i1 = min(i0 + 1, plen - 1);
        sh_i0[tid] = i0; sh_i1[tid] = i1;
        sh_w[tid] = pos - (float)i0;
    }
    __syncthreads();

    long long BN = (long long)BB * N;
    long long base = (long long)b * N + tok;

    // patches (always float32 at offset 0)
    float* pout = (float*)out;
    const float* xb = x + (long long)b * CC * LL;
    for (int q = tid; q < CC * 16; q += blockDim.x) {
        int c = q >> 4, i = q & 15;
        float v = 0.0f;
        if (valid) {
            float w = sh_w[i];
            const float* row = xb + (long long)c * LL + s;
            v = row[sh_i0[i]] * (1.0f - w) + row[sh_i1[i]] * w;
        }
        pout[base * 1024 + q] = v;
    }

    if (tid == 0) {
        float fco = 0.0f, fsp = 0.0f, r0 = 0.0f, r1 = 0.0f, r2 = 0.0f;
        int vs = 0, ve = 0;
        if (valid) {
            vs = s; ve = e;
            fco = (float)(((double)s + (double)e - 1.0) * 0.5 / 8191.0);
            fsp = (float)((double)(e - s) / 8192.0);
            r0 = g_rgm[b][tok][0]; r1 = g_rgm[b][tok][1]; r2 = g_rgm[b][tok][2];
        }
        if (layout == 0) {
            float* o = (float*)out;
            long long M = BN * 1024;
            o[M + base] = valid ? 1.0f : 0.0f;
            o[M + BN + base] = (float)vs;
            o[M + 2 * BN + base] = (float)ve;
            o[M + 3 * BN + base] = fco;
            o[M + 4 * BN + base] = fsp;
            o[M + 5 * BN + base * 3 + 0] = r0;
            o[M + 5 * BN + base * 3 + 1] = r1;
            o[M + 5 * BN + base * 3 + 2] = r2;
            if (tok == 0) o[M + 8 * BN + b] = (float)nt;
        } else if (layout == 1) {
            long long off_m = 4096LL * BN;
            long long off_so = off_m + BN;
            long long off_eo = off_so + 4 * BN;
            long long off_co = off_eo + 4 * BN;
            long long off_sp = off_co + 4 * BN;
            long long off_rg = off_sp + 4 * BN;
            long long off_nt = off_rg + 12 * BN;
            out[off_m + base] = valid ? 1 : 0;
            ((int*)(out + off_so))[base] = vs;
            ((int*)(out + off_eo))[base] = ve;
            ((float*)(out + off_co))[base] = fco;
            ((float*)(out + off_sp))[base] = fsp;
            ((float*)(out + off_rg))[base * 3 + 0] = r0;
            ((float*)(out + off_rg))[base * 3 + 1] = r1;
            ((float*)(out + off_rg))[base * 3 + 2] = r2;
            if (tok == 0) ((int*)(out + off_nt))[b] = nt;
        } else {
            long long off_m = 4096LL * BN;
            long long off_so = off_m + BN;
            long long off_eo = off_so + 8 * BN;
            long long off_co = off_eo + 8 * BN;
            long long off_sp = off_co + 4 * BN;
            long long off_rg = off_sp + 4 * BN;
            long long off_nt = off_rg + 12 * BN;
            out[off_m + base] = valid ? 1 : 0;
            ((long long*)(out + off_so))[base] = vs;
            ((long long*)(out + off_eo))[base] = ve;
            ((float*)(out + off_co))[base] = fco;
            ((float*)(out + off_sp))[base] = fsp;
            ((float*)(out + off_rg))[base * 3 + 0] = r0;
            ((float*)(out + off_rg))[base * 3 + 1] = r1;
            ((float*)(out + off_rg))[base * 3 + 2] = r2;
            if (tok == 0) ((long long*)(out + off_nt))[b] = (long long)nt;
        }
    }
}

// ---------------- launch ----------------
extern "C" void kernel_launch(void* const* d_in, const int* in_sizes, int n_in,
                              void* d_out, int out_size) {
    const float* x = (const float*)d_in[0];

    long long os = (long long)out_size;
    long long N = 0;
    int layout = 0;
    if ((os - 32) % 33024 == 0 && (os - 32) / 33024 >= 1 && (os - 32) / 33024 <= 4096) {
        N = (os - 32) / 33024; layout = 0;
    } else if ((os - 128) % 132000 == 0 && (os - 128) / 132000 >= 1 && (os - 128) / 132000 <= 4096) {
        N = (os - 128) / 132000; layout = 1;
    } else if ((os - 256) % 132256 == 0 && (os - 256) / 132256 >= 1 && (os - 256) / 132256 <= 4096) {
        N = (os - 256) / 132256; layout = 2;
    } else {
        N = os / 33024; if (N < 1) N = 1; layout = 0;
    }

    const int DP_SMEM = 69888;
    const int FFT_SMEM = 163840;
    cudaFuncSetAttribute(k_dp, cudaFuncAttributeMaxDynamicSharedMemorySize, DP_SMEM);
    cudaFuncSetAttribute(k_segstats, cudaFuncAttributeMaxDynamicSharedMemorySize, FFT_SMEM);

    k_init<<<1, 32>>>();
    k_agg<<<dim3(32, BB), 256>>>(x);
    k_winfeat<<<dim3(128, BB), 256>>>();
    k_dp<<<BB, 1024, DP_SMEM>>>();
    k_segstats<<<dim3(64, BB), 512, FFT_SMEM>>>();
    k_tokens<<<BB, 32>>>();
    k_write<<<dim3((unsigned)N, BB), 256>>>(x, (char*)d_out, N, layout);
}

// round 3
// speedup vs baseline: 2.8998x; 2.8998x over previous
#include <cuda_runtime.h>
#include <math.h>
#include <float.h>
#include <stdint.h>

#define BB 32
#define CC 64
#define LL 8192
#define NWIN 1021
#define NP2 1022
#define MAXSEG 1024
#define MAXTOK 2176
#define FULLM 0xffffffffu

// ---------------- device scratch ----------------
__device__ float  g_agg[BB][LL];
__device__ float  g_feat[BB][NWIN][3];
__device__ double g_c32[32], g_s32[32];
__device__ int    g_seg_s[BB][MAXSEG], g_seg_e[BB][MAXSEG], g_nseg[BB];
__device__ float  g_dp[BB][MAXSEG], g_bw[BB][MAXSEG];
__device__ int    g_ts[BB][MAXTOK], g_te[BB][MAXTOK];
__device__ float  g_rgm[BB][MAXTOK][3];
__device__ int    g_ntok[BB];

// ---------------- init: 32-pt DFT twiddles (fp64) ----------------
__global__ void k_init() {
    int t = threadIdx.x;
    double s, c;
    sincospi((double)t / 16.0, &s, &c);
    g_c32[t] = c;
    g_s32[t] = s;
}

// ---------------- agg = mean over channels (sequential fp32, numpy order) ----------------
__global__ void k_agg(const float* __restrict__ x) {
    int b = blockIdx.y;
    int t = blockIdx.x * blockDim.x + threadIdx.x;
    const float* xb = x + ((size_t)b * CC) * LL + t;
    float s = 0.0f;
    #pragma unroll 1
    for (int c = 0; c < CC; c++) s += xb[(size_t)c * LL];
    g_agg[b][t] = s / 64.0f;
}

// ---------------- window features: 1 warp per window, fp64 (decision-critical) ----------
// lanes 0..15 vs 16..31 split the 32-sample time sum (halves fp64 warp-instrs);
// numpy pairwise-sum16 reproduced by xor-shuffles 8,1,2,4 within each 16-lane half.
__global__ void k_winfeat() {
    int b = blockIdx.y;
    int widx = blockIdx.x * 8 + (threadIdx.x >> 5);
    if (widx >= NWIN) return;
    int lane = threadIdx.x & 31;
    int k = (lane & 15) + 1;
    int th = lane >> 4;
    int st = widx * 8;

    double re = 0.0, im = 0.0;
    int t0 = th * 16;
    #pragma unroll 1
    for (int t = t0; t < t0 + 16; t++) {
        double a = (double)g_agg[b][st + t];
        int id = (k * t) & 31;
        re = fma(a, g_c32[id], re);
        im = fma(a, g_s32[id], im);
    }
    re = re + __shfl_xor_sync(FULLM, re, 16);
    im = im + __shfl_xor_sync(FULLM, im, 16);
    double p = re * re + im * im;

    double tot = p;
    tot = tot + __shfl_xor_sync(FULLM, tot, 8);
    tot = tot + __shfl_xor_sync(FULLM, tot, 1);
    tot = tot + __shfl_xor_sync(FULLM, tot, 2);
    tot = tot + __shfl_xor_sync(FULLM, tot, 4);

    double prob = p / (tot + 1e-12);
    double f = (double)k / 32.0;

    double cen = prob * f;
    cen = cen + __shfl_xor_sync(FULLM, cen, 8);
    cen = cen + __shfl_xor_sync(FULLM, cen, 1);
    cen = cen + __shfl_xor_sync(FULLM, cen, 2);
    cen = cen + __shfl_xor_sync(FULLM, cen, 4);

    double dev = f - cen;
    double s2 = prob * (dev * dev);
    s2 = s2 + __shfl_xor_sync(FULLM, s2, 8);
    s2 = s2 + __shfl_xor_sync(FULLM, s2, 1);
    s2 = s2 + __shfl_xor_sync(FULLM, s2, 2);
    s2 = s2 + __shfl_xor_sync(FULLM, s2, 4);

    if (lane == 0) {
        double spread = sqrt(fmax(s2, 0.0));
        g_feat[b][widx][0] = (float)cen;
        g_feat[b][widx][1] = (float)(2.0 * spread);
        g_feat[b][widx][2] = (float)log1p(tot / 32.0);
    }
}

// ---------------- DP changepoints: 1 warp per batch ----------------
// fp32 fast path (min + runner-up). If runner-up within EPS of min, exact
// numpy-ordered fp64 recompute over all j. Fv recursion always numpy-exact.
extern __shared__ char dpsm[];
__global__ void __launch_bounds__(32, 1) k_dp() {
    const int n = NWIN;
    int b = blockIdx.x;
    int lane = threadIdx.x;

    double* c0d = (double*)dpsm;          // NP2 each
    double* c1d = c0d + NP2;
    double* c2d = c1d + NP2;
    double* s0d = c2d + NP2;
    double* s1d = s0d + NP2;
    double* s2d = s1d + NP2;
    double* Fvd = s2d + NP2;
    float*  c0f = (float*)(Fvd + NP2);
    float*  c1f = c0f + NP2;
    float*  c2f = c1f + NP2;
    float*  G32 = c2f + NP2;
    float*  rcf = G32 + NP2;
    int*    par = (int*)(rcf + NP2);

    // prefix chains: lanes 0-2 cumsum(feat), lanes 3-5 cumsum(feat^2), numpy-sequential fp64
    if (lane < 3) {
        double* cd = (lane == 0) ? c0d : (lane == 1) ? c1d : c2d;
        float*  cf = (lane == 0) ? c0f : (lane == 1) ? c1f : c2f;
        double acc = 0.0;
        cd[0] = 0.0; cf[0] = 0.0;
        for (int i = 0; i < n; i++) {
            acc = __dadd_rn(acc, (double)g_feat[b][i][lane]);
            cd[i + 1] = acc; cf[i + 1] = (float)acc;
        }
    } else if (lane < 6) {
        int c = lane - 3;
        double* sd = (c == 0) ? s0d : (c == 1) ? s1d : s2d;
        double acc = 0.0;
        sd[0] = 0.0;
        for (int i = 0; i < n; i++) {
            double v = (double)g_feat[b][i][c];
            acc = __dadd_rn(acc, __dmul_rn(v, v));
            sd[i + 1] = acc;
        }
    }
    for (int i = lane; i <= n; i += 32) rcf[i] = (i > 0) ? (1.0f / (float)i) : 0.0f;
    if (lane == 0) { Fvd[0] = 0.0; G32[0] = 6.0f; par[0] = 0; }
    __syncwarp();

    auto exactv = [&](int tt, int jj) -> double {
        double d0 = __dsub_rn(c0d[tt], c0d[jj]);
        double d1 = __dsub_rn(c1d[tt], c1d[jj]);
        double d2 = __dsub_rn(c2d[tt], c2d[jj]);
        double dssq = __dadd_rn(__dadd_rn(__dmul_rn(d0, d0), __dmul_rn(d1, d1)), __dmul_rn(d2, d2));
        double q0 = __dsub_rn(s0d[tt], s0d[jj]);
        double q1 = __dsub_rn(s1d[tt], s1d[jj]);
        double q2 = __dsub_rn(s2d[tt], s2d[jj]);
        double ds2 = __dadd_rn(__dadd_rn(q0, q1), q2);
        double cost = __dsub_rn(ds2, __ddiv_rn(dssq, (double)(tt - jj)));
        return __dadd_rn(__dadd_rn(Fvd[jj], cost), 3.0);
    };

    for (int t = 1; t <= n; t++) {
        float ct0 = c0f[t], ct1 = c1f[t], ct2 = c2f[t];
        float v1 = FLT_MAX, v2 = FLT_MAX;
        int i1 = 0x7fffffff;
        for (int j = lane; j < t; j += 32) {
            float d0 = ct0 - c0f[j];
            float d1 = ct1 - c1f[j];
            float d2 = ct2 - c2f[j];
            float sq = fmaf(d0, d0, fmaf(d1, d1, d2 * d2));
            float v = fmaf(-sq, rcf[t - j], G32[j]);
            if (v < v1) { v2 = v1; v1 = v; i1 = j; }
            else v2 = fminf(v2, v);
        }
        #pragma unroll
        for (int o = 16; o; o >>= 1) {
            float ov1 = __shfl_down_sync(FULLM, v1, o);
            float ov2 = __shfl_down_sync(FULLM, v2, o);
            int oi = __shfl_down_sync(FULLM, i1, o);
            if (ov1 < v1 || (ov1 == v1 && oi < i1)) { v2 = fminf(v1, ov2); v1 = ov1; i1 = oi; }
            else v2 = fminf(v2, ov1);
        }
        int fb = __shfl_sync(FULLM, (v2 - v1 <= 1e-3f) ? 1 : 0, 0);
        if (!fb) {
            if (lane == 0) {
                double val = exactv(t, i1);
                Fvd[t] = val;
                double At = __dadd_rn(__dadd_rn(s0d[t], s1d[t]), s2d[t]);
                G32[t] = (float)((val + 6.0) - At);
                par[t] = i1;
            }
        } else {
            double bv = DBL_MAX; int bi = 0x7fffffff;
            for (int j = lane; j < t; j += 32) {
                double v = exactv(t, j);
                if (v < bv) { bv = v; bi = j; }
            }
            #pragma unroll
            for (int o = 16; o; o >>= 1) {
                double ov = __shfl_down_sync(FULLM, bv, o);
                int oi = __shfl_down_sync(FULLM, bi, o);
                if (ov < bv || (ov == bv && oi < bi)) { bv = ov; bi = oi; }
            }
            if (lane == 0) {
                Fvd[t] = bv;
                double At = __dadd_rn(__dadd_rn(s0d[t], s1d[t]), s2d[t]);
                G32[t] = (float)((bv + 6.0) - At);
                par[t] = bi;
            }
        }
        __syncwarp();
    }

    if (lane == 0) {
        int* chain = (int*)c0d;   // reuse
        int cl = 0, t = n;
        chain[cl++] = t;
        while (t > 0) { t = par[t]; chain[cl++] = t; }
        int last = 0, nseg = 0;
        for (int q = cl - 2; q >= 1; q--) {
            int w = chain[q];
            if (w < 0 || w >= NWIN) continue;
            int ti = w * 8;
            if (ti <= last) continue;
            if (ti - last < 8) continue;
            if (LL - ti < 8) continue;
            g_seg_s[b][nseg] = last; g_seg_e[b][nseg] = ti; nseg++;
            last = ti;
        }
        g_seg_s[b][nseg] = last; g_seg_e[b][nseg] = LL; nseg++;
        g_nseg[b] = nseg;
    }
}

// ---------------- block reduce helpers (512 threads = 16 warps) ----------------
__device__ __forceinline__ double block_sum512(double v, double* sh) {
    int tid = threadIdx.x;
    #pragma unroll
    for (int o = 16; o; o >>= 1) v += __shfl_down_sync(FULLM, v, o);
    if ((tid & 31) == 0) sh[tid >> 5] = v;
    __syncthreads();
    if (tid < 32) {
        double w = (tid < 16) ? sh[tid] : 0.0;
        #pragma unroll
        for (int o = 8; o; o >>= 1) w += __shfl_down_sync(FULLM, w, o);
        if (tid == 0) sh[0] = w;
    }
    __syncthreads();
    double r = sh[0];
    __syncthreads();
    return r;
}

__device__ __forceinline__ int block_argmax512f(float v, int k, float* shv, int* shk) {
    int tid = threadIdx.x;
    #pragma unroll
    for (int o = 16; o; o >>= 1) {
        float ov = __shfl_down_sync(FULLM, v, o);
        int ok = __shfl_down_sync(FULLM, k, o);
        if (ov > v || (ov == v && ok < k)) { v = ov; k = ok; }
    }
    if ((tid & 31) == 0) { shv[tid >> 5] = v; shk[tid >> 5] = k; }
    __syncthreads();
    if (tid < 32) {
        float w = (tid < 16) ? shv[tid] : -FLT_MAX;
        int kk = (tid < 16) ? shk[tid] : 0x7fffffff;
        #pragma unroll
        for (int o = 8; o; o >>= 1) {
            float ov = __shfl_down_sync(FULLM, w, o);
            int ok = __shfl_down_sync(FULLM, kk, o);
            if (ov > w || (ov == w && ok < kk)) { w = ov; kk = ok; }
        }
        if (tid == 0) shk[0] = kk;
    }
    __syncthreads();
    int r = shk[0];
    __syncthreads();
    return r;
}

// ---------------- per-segment spectral stats: fp32 FFT + table twiddles ----------------
extern __shared__ char ssm[];
__global__ void __launch_bounds__(512, 1) k_segstats() {
    int b = blockIdx.y;
    int tid = threadIdx.x;
    const int T = 512;
    int nseg = g_nseg[b];

    float* re  = (float*)ssm;     // 8192
    float* im  = re + 8192;       // 8192
    float* twc = im + 8192;       // 4096 (pow2 table / nonpow2 parr)
    float* tws = twc + 4096;      // 4096
    __shared__ double s_rv[16];
    __shared__ float  s_fv[16];
    __shared__ int    s_rk[16];

    for (int seg = blockIdx.x; seg < nseg; seg += gridDim.x) {
        int s = g_seg_s[b][seg], e = g_seg_e[b][seg];
        int m = e - s;
        int K = m >> 1;
        double tot, cen, s2;
        int kbest;

        if ((m & (m - 1)) == 0) {
            int lg = __ffs(m) - 1;
            for (int i = tid; i < m; i += T) {
                unsigned r = __brev((unsigned)i) >> (32 - lg);
                re[r] = g_agg[b][s + i];
                im[r] = 0.0f;
            }
            for (int k = tid; k < (m >> 1); k += T) {
                float sv, cv;
                sincospif(-2.0f * (float)k / (float)m, &sv, &cv);
                twc[k] = cv; tws[k] = sv;
            }
            __syncthreads();
            for (int len = 2; len <= m; len <<= 1) {
                int half = len >> 1;
                int step = m / len;
                for (int idx = tid; idx < (m >> 1); idx += T) {
                    int j = idx & (half - 1);
                    int pos = 2 * idx - j;
                    int p2 = pos + half;
                    float wc = twc[j * step], ws = tws[j * step];
                    float xr = re[p2], xi = im[p2];
                    float tr = wc * xr - ws * xi;
                    float ti = wc * xi + ws * xr;
                    float ur = re[pos], ui = im[pos];
                    re[pos] = ur + tr; im[pos] = ui + ti;
                    re[p2] = ur - tr;  im[p2] = ui - ti;
                }
                __syncthreads();
            }
            double lt = 0.0; float lm = -FLT_MAX; int lk = 0x7fffffff;
            for (int k = 1 + tid; k <= K; k += T) {
                float pr = re[k] * re[k] + im[k] * im[k];
                lt += (double)pr;
                if (pr > lm) { lm = pr; lk = k; }
            }
            tot = block_sum512(lt, s_rv);
            kbest = block_argmax512f(lm, lk, s_fv, s_rk);
            float invden = (float)(1.0 / (tot + 1e-12));
            float invm = 1.0f / (float)m;
            double lc = 0.0;
            for (int k = 1 + tid; k <= K; k += T) {
                float pr = re[k] * re[k] + im[k] * im[k];
                lc += (double)((pr * invden) * ((float)k * invm));
            }
            cen = block_sum512(lc, s_rv);
            float cenf = (float)cen;
            double ls = 0.0;
            for (int k = 1 + tid; k <= K; k += T) {
                float pr = re[k] * re[k] + im[k] * im[k];
                float dev = (float)k * invm - cenf;
                ls += (double)((pr * invden) * (dev * dev));
            }
            s2 = block_sum512(ls, s_rv);
        } else {
            // direct fp32 DFT: table in re/im, power in twc
            for (int t = tid; t < m; t += T) {
                float sv, cv;
                sincospif(-2.0f * (float)t / (float)m, &sv, &cv);
                re[t] = cv; im[t] = sv;
            }
            __syncthreads();
            for (int k = 1 + tid; k <= K; k += T) {
                float rr = 0.0f, ri = 0.0f;
                int idx = 0;
                for (int t = 0; t < m; t++) {
                    float a = g_agg[b][s + t];
                    rr = fmaf(a, re[idx], rr);
                    ri = fmaf(a, im[idx], ri);
                    idx += k; if (idx >= m) idx -= m;
                }
                twc[k - 1] = rr * rr + ri * ri;
            }
            __syncthreads();
            double lt = 0.0; float lm = -FLT_MAX; int lk = 0x7fffffff;
            for (int k = 1 + tid; k <= K; k += T) {
                float pr = twc[k - 1];
                lt += (double)pr;
                if (pr > lm) { lm = pr; lk = k; }
            }
            tot = block_sum512(lt, s_rv);
            kbest = block_argmax512f(lm, lk, s_fv, s_rk);
            float invden = (float)(1.0 / (tot + 1e-12));
            float invm = 1.0f / (float)m;
            double lc = 0.0;
            for (int k = 1 + tid; k <= K; k += T)
                lc += (double)((twc[k - 1] * invden) * ((float)k * invm));
            cen = block_sum512(lc, s_rv);
            float cenf = (float)cen;
            double ls = 0.0;
            for (int k = 1 + tid; k <= K; k += T) {
                float dev = (float)k * invm - cenf;
                ls += (double)((twc[k - 1] * invden) * (dev * dev));
            }
            s2 = block_sum512(ls, s_rv);
        }
        if (tid == 0) {
            double spread = sqrt(fmax(s2, 0.0));
            g_dp[b][seg] = (float)((double)m / (double)kbest);
            g_bw[b][seg] = (float)(2.0 * spread);
        }
        __syncthreads();
    }
}

// ---------------- token generation ----------------
__global__ void k_tokens() {
    int b = blockIdx.x;
    if (threadIdx.x != 0) return;
    int nseg = g_nseg[b];
    int n = 0;
    for (int sg = 0; sg < nseg; sg++) {
        int s = g_seg_s[b][sg], e = g_seg_e[b][sg];
        double dp = (double)g_dp[b][sg];
        double bw = (double)g_bw[b][sg];
        double raw = dp / (1.0 + bw);
        long long p = 2LL * (long long)rint(raw / 2.0);  // Python round: half-to-even
        long long pl = p;
        if (pl > 64) pl = 64;
        if (pl < 8) pl = 8;
        float r0 = (float)(dp / 8192.0);
        float r1 = g_bw[b][sg];
        float r2 = (float)((double)(e - s) / 8192.0);
        int ipl = (int)pl;
        int nf = (e - s) / ipl;
        for (int i = 0; i < nf && n < MAXTOK; i++) {
            g_ts[b][n] = s + i * ipl;
            g_te[b][n] = s + (i + 1) * ipl;
            g_rgm[b][n][0] = r0; g_rgm[b][n][1] = r1; g_rgm[b][n][2] = r2;
            n++;
        }
        if (nf * ipl < e - s && n < MAXTOK) {
            g_ts[b][n] = s + nf * ipl;
            g_te[b][n] = e;
            g_rgm[b][n][0] = r0; g_rgm[b][n][1] = r1; g_rgm[b][n][2] = r2;
            n++;
        }
    }
    g_ntok[b] = n;
}

// ---------------- output writer ----------------
__global__ void k_write(const float* __restrict__ x, char* __restrict__ out,
                        long long N, int layout) {
    int b = blockIdx.y;
    long long tok = blockIdx.x;
    int tid = threadIdx.x;
    int nt = g_ntok[b];
    bool valid = tok < (long long)nt;

    __shared__ int sh_i0[16], sh_i1[16];
    __shared__ float sh_w[16];

    int s = 0, e = 16;
    if (valid) { s = g_ts[b][tok]; e = g_te[b][tok]; }
    int plen = e - s;

    if (tid < 16) {
        float scale = (float)((double)plen / 16.0);
        float pos = ((float)tid + 0.5f) * scale - 0.5f;
        pos = fminf(fmaxf(pos, 0.0f), (float)(plen - 1));
        int i0 = (int)floorf(pos);
        int i1 = min(i0 + 1, plen - 1);
        sh_i0[tid] = i0; sh_i1[tid] = i1;
        sh_w[tid] = pos - (float)i0;
    }
    __syncthreads();

    long long BN = (long long)BB * N;
    long long base = (long long)b * N + tok;

    float* pout = (float*)out;
    const float* xb = x + (long long)b * CC * LL;
    for (int q = tid; q < CC * 16; q += blockDim.x) {
        int c = q >> 4, i = q & 15;
        float v = 0.0f;
        if (valid) {
            float w = sh_w[i];
            const float* row = xb + (long long)c * LL + s;
            v = row[sh_i0[i]] * (1.0f - w) + row[sh_i1[i]] * w;
        }
        pout[base * 1024 + q] = v;
    }

    if (tid == 0) {
        float fco = 0.0f, fsp = 0.0f, r0 = 0.0f, r1 = 0.0f, r2 = 0.0f;
        int vs = 0, ve = 0;
        if (valid) {
            vs = s; ve = e;
            fco = (float)(((double)s + (double)e - 1.0) * 0.5 / 8191.0);
            fsp = (float)((double)(e - s) / 8192.0);
            r0 = g_rgm[b][tok][0]; r1 = g_rgm[b][tok][1]; r2 = g_rgm[b][tok][2];
        }
        if (layout == 0) {
            float* o = (float*)out;
            long long M = BN * 1024;
            o[M + base] = valid ? 1.0f : 0.0f;
            o[M + BN + base] = (float)vs;
            o[M + 2 * BN + base] = (float)ve;
            o[M + 3 * BN + base] = fco;
            o[M + 4 * BN + base] = fsp;
            o[M + 5 * BN + base * 3 + 0] = r0;
            o[M + 5 * BN + base * 3 + 1] = r1;
            o[M + 5 * BN + base * 3 + 2] = r2;
            if (tok == 0) o[M + 8 * BN + b] = (float)nt;
        } else if (layout == 1) {
            long long off_m = 4096LL * BN;
            long long off_so = off_m + BN;
            long long off_eo = off_so + 4 * BN;
            long long off_co = off_eo + 4 * BN;
            long long off_sp = off_co + 4 * BN;
            long long off_rg = off_sp + 4 * BN;
            long long off_nt = off_rg + 12 * BN;
            out[off_m + base] = valid ? 1 : 0;
            ((int*)(out + off_so))[base] = vs;
            ((int*)(out + off_eo))[base] = ve;
            ((float*)(out + off_co))[base] = fco;
            ((float*)(out + off_sp))[base] = fsp;
            ((float*)(out + off_rg))[base * 3 + 0] = r0;
            ((float*)(out + off_rg))[base * 3 + 1] = r1;
            ((float*)(out + off_rg))[base * 3 + 2] = r2;
            if (tok == 0) ((int*)(out + off_nt))[b] = nt;
        } else {
            long long off_m = 4096LL * BN;
            long long off_so = off_m + BN;
            long long off_eo = off_so + 8 * BN;
            long long off_co = off_eo + 8 * BN;
            long long off_sp = off_co + 4 * BN;
            long long off_rg = off_sp + 4 * BN;
            long long off_nt = off_rg + 12 * BN;
            out[off_m + base] = valid ? 1 : 0;
            ((long long*)(out + off_so))[base] = vs;
            ((long long*)(out + off_eo))[base] = ve;
            ((float*)(out + off_co))[base] = fco;
            ((float*)(out + off_sp))[base] = fsp;
            ((float*)(out + off_rg))[base * 3 + 0] = r0;
            ((float*)(out + off_rg))[base * 3 + 1] = r1;
            ((float*)(out + off_rg))[base * 3 + 2] = r2;
            if (tok == 0) ((long long*)(out + off_nt))[b] = (long long)nt;
        }
    }
}

// ---------------- launch ----------------
extern "C" void kernel_launch(void* const* d_in, const int* in_sizes, int n_in,
                              void* d_out, int out_size) {
    const float* x = (const float*)d_in[0];

    long long os = (long long)out_size;
    long long N = 0;
    int layout = 0;
    if ((os - 32) % 33024 == 0 && (os - 32) / 33024 >= 1 && (os - 32) / 33024 <= 4096) {
        N = (os - 32) / 33024; layout = 0;
    } else if ((os - 128) % 132000 == 0 && (os - 128) / 132000 >= 1 && (os - 128) / 132000 <= 4096) {
        N = (os - 128) / 132000; layout = 1;
    } else if ((os - 256) % 132256 == 0 && (os - 256) / 132256 >= 1 && (os - 256) / 132256 <= 4096) {
        N = (os - 256) / 132256; layout = 2;
    } else {
        N = os / 33024; if (N < 1) N = 1; layout = 0;
    }

    // k_dp smem: 7 fp64 arrays (NP2) + 5 fp32 arrays (NP2) + int par (NP2)
    const int DP_SMEM = NP2 * (7 * 8 + 5 * 4 + 4);   // 81760
    const int FFT_SMEM = (8192 * 2 + 4096 * 2) * 4;  // 98304
    cudaFuncSetAttribute(k_dp, cudaFuncAttributeMaxDynamicSharedMemorySize, DP_SMEM);
    cudaFuncSetAttribute(k_segstats, cudaFuncAttributeMaxDynamicSharedMemorySize, FFT_SMEM);

    k_init<<<1, 32>>>();
    k_agg<<<dim3(32, BB), 256>>>(x);
    k_winfeat<<<dim3(128, BB), 256>>>();
    k_dp<<<BB, 32, DP_SMEM>>>();
    k_segstats<<<dim3(16, BB), 512, FFT_SMEM>>>();
    k_tokens<<<BB, 32>>>();
    k_write<<<dim3((unsigned)N, BB), 256>>>(x, (char*)d_out, N, layout);
}